// round 1
// baseline (speedup 1.0000x reference)
#include <cuda_runtime.h>

// Problem constants (from reference: B=64, S=512, H=768, W=MAX_WORD_LEN=256,
// VOCAB=50000, WE=300)
constexpr int B   = 64;
constexpr int S   = 512;
constexpr int H   = 768;
constexpr int W   = 256;
constexpr int WE  = 300;

constexpr int H4   = H  / 4;       // 192 float4 per transformer row
constexpr int WE4  = WE / 4;       // 75  float4 per w2v row
constexpr int OUT4 = H4 + WE4;     // 267 float4 per output row (1068 floats)

// One CTA per (batch, word). token_ids[b, :] is sorted, so the subword tokens
// belonging to word w are a contiguous [start, end) range found by binary
// search. The CTA then computes the segment mean over H=768 (vectorized
// float4) and appends the gathered w2v row, writing the full 1068-float
// output row coalesced.
__global__ void __launch_bounds__(256)
embeddings_fused_kernel(const float4* __restrict__ hidden,     // [B, S, H4]
                        const float4* __restrict__ w2v,        // [VOCAB, WE4]
                        const int*    __restrict__ token_ids,  // [B, S]
                        const int*    __restrict__ word_ids,   // [B, W]
                        float4*       __restrict__ out)        // [B, W, OUT4]
{
    const int bw = blockIdx.x;          // 0 .. B*W-1
    const int b  = bw >> 8;             // / W (W == 256)
    const int w  = bw & (W - 1);

    const int* __restrict__ trow = token_ids + b * S;

    // lower_bound(w): first index with trow[i] >= w
    int lo = 0, hi = S;
    while (lo < hi) {
        int mid = (lo + hi) >> 1;
        if (trow[mid] < w) lo = mid + 1; else hi = mid;
    }
    const int start = lo;
    // upper_bound(w): first index with trow[i] > w
    hi = S;
    while (lo < hi) {
        int mid = (lo + hi) >> 1;
        if (trow[mid] <= w) lo = mid + 1; else hi = mid;
    }
    const int end   = lo;
    const int count = end - start;
    const float inv = (count > 0) ? (1.0f / (float)count) : 0.0f;

    const int wid = word_ids[b * W + w];

    const float4* __restrict__ hbase = hidden + ((size_t)b * S + start) * H4;
    const float4* __restrict__ grow  = w2v + (size_t)wid * WE4;
    float4* __restrict__ orow        = out + (size_t)bw * OUT4;

    for (int j = threadIdx.x; j < OUT4; j += 256) {
        if (j < H4) {
            // segment mean over [start, end) tokens, column chunk j
            float4 acc = make_float4(0.f, 0.f, 0.f, 0.f);
            const float4* p = hbase + j;
            for (int t = 0; t < count; ++t, p += H4) {
                float4 v = *p;
                acc.x += v.x; acc.y += v.y; acc.z += v.z; acc.w += v.w;
            }
            acc.x *= inv; acc.y *= inv; acc.z *= inv; acc.w *= inv;
            orow[j] = acc;
        } else {
            // w2v gather
            orow[j] = grow[j - H4];
        }
    }
}

extern "C" void kernel_launch(void* const* d_in, const int* in_sizes, int n_in,
                              void* d_out, int out_size)
{
    const float4* hidden    = (const float4*)d_in[0];   // [B,S,H] f32
    const float4* w2v       = (const float4*)d_in[1];   // [VOCAB,WE] f32
    const int*    token_ids = (const int*)d_in[2];      // [B,S]
    const int*    word_ids  = (const int*)d_in[3];      // [B,W]
    float4*       out       = (float4*)d_out;           // [B,W,H+WE] f32

    embeddings_fused_kernel<<<B * W, 256>>>(hidden, w2v, token_ids, word_ids, out);
}

// round 5
// speedup vs baseline: 1.8061x; 1.8061x over previous
#include <cuda_runtime.h>

// Problem constants (B=64, S=512, H=768, W=MAX_WORD_LEN=256, VOCAB=50000, WE=300)
constexpr int B   = 64;
constexpr int S   = 512;
constexpr int H   = 768;
constexpr int W   = 256;
constexpr int WE  = 300;

constexpr int H4   = H  / 4;       // 192 float4 per transformer row
constexpr int WE4  = WE / 4;       // 75  float4 per w2v row
constexpr int OUT4 = H4 + WE4;     // 267 float4 per output row (1068 floats)

// Segment boundaries: g_start[b*(W+1) + w] = lower_bound(token_ids[b,:], w).
// Token values are in [0, W), so lower_bound(W) == S for the sentinel entry.
__device__ int g_start[B * (W + 1)];

// ---------------------------------------------------------------------------
// Kernel 1: one thread per (b, w) for w in [0, W] — full binary search over
// the sorted token row (plain while loop: 512-range needs 10 halvings; the
// fixed 9-iteration unroll in the previous round was the correctness bug).
// 16448 threads total; runs in ~2 us.
// ---------------------------------------------------------------------------
__global__ void __launch_bounds__(256)
seg_bounds_kernel(const int* __restrict__ token_ids)   // [B, S]
{
    const int idx = blockIdx.x * blockDim.x + threadIdx.x;
    if (idx >= B * (W + 1)) return;
    const int b = idx / (W + 1);
    const int w = idx - b * (W + 1);

    const int* __restrict__ trow = token_ids + b * S;
    int lo = 0, hi = S;
    while (lo < hi) {
        int mid = (lo + hi) >> 1;
        if (trow[mid] < w) lo = mid + 1; else hi = mid;
    }
    g_start[idx] = lo;
}

// ---------------------------------------------------------------------------
// Kernel 2: one CTA per (batch, word). Reads the precomputed [start, end)
// range (2 broadcast ints), computes the H=768 segment mean with float4 loads
// (unrolled x2 with dual accumulators for MLP), and appends the gathered
// w2v row. Fully coalesced loads and stores; no redundant index math.
// ---------------------------------------------------------------------------
__global__ void __launch_bounds__(256)
embeddings_fused_kernel(const float4* __restrict__ hidden,     // [B, S, H4]
                        const float4* __restrict__ w2v,        // [VOCAB, WE4]
                        const int*    __restrict__ word_ids,   // [B, W]
                        float4*       __restrict__ out)        // [B, W, OUT4]
{
    const int bw = blockIdx.x;          // 0 .. B*W-1
    const int b  = bw >> 8;             // / W (W == 256)
    const int w  = bw & (W - 1);

    const int sidx  = b * (W + 1) + w;
    const int start = g_start[sidx];
    const int end   = g_start[sidx + 1];
    const int count = end - start;
    const float inv = (count > 0) ? (1.0f / (float)count) : 0.0f;

    const int wid = word_ids[b * W + w];

    const float4* __restrict__ hbase = hidden + ((size_t)b * S + start) * H4;
    const float4* __restrict__ grow  = w2v + (size_t)wid * WE4;
    float4* __restrict__ orow        = out + (size_t)bw * OUT4;

    for (int j = threadIdx.x; j < OUT4; j += 256) {
        if (j < H4) {
            // segment mean over [start, end) tokens, column chunk j
            float4 acc0 = make_float4(0.f, 0.f, 0.f, 0.f);
            float4 acc1 = make_float4(0.f, 0.f, 0.f, 0.f);
            const float4* p = hbase + j;
            int t = 0;
            for (; t + 2 <= count; t += 2, p += 2 * H4) {
                float4 v0 = p[0];
                float4 v1 = p[H4];
                acc0.x += v0.x; acc0.y += v0.y; acc0.z += v0.z; acc0.w += v0.w;
                acc1.x += v1.x; acc1.y += v1.y; acc1.z += v1.z; acc1.w += v1.w;
            }
            if (t < count) {
                float4 v0 = p[0];
                acc0.x += v0.x; acc0.y += v0.y; acc0.z += v0.z; acc0.w += v0.w;
            }
            float4 r;
            r.x = (acc0.x + acc1.x) * inv;
            r.y = (acc0.y + acc1.y) * inv;
            r.z = (acc0.z + acc1.z) * inv;
            r.w = (acc0.w + acc1.w) * inv;
            orow[j] = r;
        } else {
            // w2v gather (row-contiguous, coalesced)
            orow[j] = grow[j - H4];
        }
    }
}

extern "C" void kernel_launch(void* const* d_in, const int* in_sizes, int n_in,
                              void* d_out, int out_size)
{
    const float4* hidden    = (const float4*)d_in[0];   // [B,S,H] f32
    const float4* w2v       = (const float4*)d_in[1];   // [VOCAB,WE] f32
    const int*    token_ids = (const int*)d_in[2];      // [B,S]
    const int*    word_ids  = (const int*)d_in[3];      // [B,W]
    float4*       out       = (float4*)d_out;           // [B,W,H+WE] f32

    const int nb = (B * (W + 1) + 255) / 256;           // 65 blocks
    seg_bounds_kernel<<<nb, 256>>>(token_ids);
    embeddings_fused_kernel<<<B * W, 256>>>(hidden, w2v, word_ids, out);
}

// round 7
// speedup vs baseline: 2.3394x; 1.2952x over previous
#include <cuda_runtime.h>

// Problem constants (B=64, S=512, H=768, W=MAX_WORD_LEN=256, VOCAB=50000, WE=300)
constexpr int B   = 64;
constexpr int S   = 512;
constexpr int H   = 768;
constexpr int W   = 256;
constexpr int WE  = 300;

constexpr int H4   = H  / 4;       // 192 float4 per transformer row
constexpr int WE4  = WE / 4;       // 75  float4 per w2v row
constexpr int OUT4 = H4 + WE4;     // 267 float4 per output row (1068 floats)

constexpr int G      = 4;          // words per CTA
constexpr int WG     = W / G;      // word-groups per batch (64)

// Segment boundaries: g_start[b*(W+1) + w] = lower_bound(token_ids[b,:], w).
__device__ int g_start[B * (W + 1)];

// ---------------------------------------------------------------------------
// Kernel 1: scatter-based bounds. One thread per (b, s). For every word value
// w in (token[s-1], token[s]], lower_bound(w) == s. The last token thread
// also covers (token[S-1], W] -> S. One coalesced pass, no binary searches.
// ---------------------------------------------------------------------------
__global__ void __launch_bounds__(256)
seg_bounds_scatter(const int* __restrict__ token_ids)   // [B, S]
{
    const int idx = blockIdx.x * blockDim.x + threadIdx.x;
    if (idx >= B * S) return;
    const int b = idx >> 9;            // / S (S == 512)
    const int s = idx & (S - 1);

    const int cur  = token_ids[idx];
    const int prev = (s == 0) ? -1 : token_ids[idx - 1];

    int* __restrict__ srow = g_start + b * (W + 1);
    for (int w = prev + 1; w <= cur; ++w) srow[w] = s;
    if (s == S - 1) {
        for (int w = cur + 1; w <= W; ++w) srow[w] = S;
    }
}

// ---------------------------------------------------------------------------
// Kernel 2: one CTA per (batch, word-group of G=4 consecutive words).
// Streams the group's contiguous token range with .cs (evict-first) loads,
// writes output rows with .cs streaming stores, and leaves L2 to the w2v
// table (60 MB, fits in 126 MB L2) so the gather is an L2 hit on replays.
// ---------------------------------------------------------------------------
__global__ void __launch_bounds__(256)
embeddings_fused_kernel(const float4* __restrict__ hidden,     // [B, S, H4]
                        const float4* __restrict__ w2v,        // [VOCAB, WE4]
                        const int*    __restrict__ word_ids,   // [B, W]
                        float4*       __restrict__ out)        // [B, W, OUT4]
{
    const int bg = blockIdx.x;          // 0 .. B*WG-1
    const int b  = bg / WG;
    const int w0 = (bg - b * WG) * G;

    const int* __restrict__ srow = g_start + b * (W + 1) + w0;

    #pragma unroll
    for (int g = 0; g < G; ++g) {
        const int w     = w0 + g;
        const int start = srow[g];
        const int end   = srow[g + 1];
        const int count = end - start;
        const float inv = (count > 0) ? (1.0f / (float)count) : 0.0f;

        const int wid = word_ids[b * W + w];

        const float4* __restrict__ hbase = hidden + ((size_t)b * S + start) * H4;
        const float4* __restrict__ grow  = w2v + (size_t)wid * WE4;
        float4* __restrict__ orow        = out + ((size_t)b * W + w) * OUT4;

        for (int j = threadIdx.x; j < OUT4; j += 256) {
            if (j < H4) {
                // segment mean over [start, end) tokens, column chunk j
                float4 acc0 = make_float4(0.f, 0.f, 0.f, 0.f);
                float4 acc1 = make_float4(0.f, 0.f, 0.f, 0.f);
                const float4* p = hbase + j;
                int t = 0;
                for (; t + 2 <= count; t += 2, p += 2 * H4) {
                    float4 v0 = __ldcs(p);
                    float4 v1 = __ldcs(p + H4);
                    acc0.x += v0.x; acc0.y += v0.y; acc0.z += v0.z; acc0.w += v0.w;
                    acc1.x += v1.x; acc1.y += v1.y; acc1.z += v1.z; acc1.w += v1.w;
                }
                if (t < count) {
                    float4 v0 = __ldcs(p);
                    acc0.x += v0.x; acc0.y += v0.y; acc0.z += v0.z; acc0.w += v0.w;
                }
                float4 r;
                r.x = (acc0.x + acc1.x) * inv;
                r.y = (acc0.y + acc1.y) * inv;
                r.z = (acc0.z + acc1.z) * inv;
                r.w = (acc0.w + acc1.w) * inv;
                __stcs(orow + j, r);
            } else {
                // w2v gather: default caching so the table stays L2-resident
                __stcs(orow + j, __ldg(grow + (j - H4)));
            }
        }
    }
}

extern "C" void kernel_launch(void* const* d_in, const int* in_sizes, int n_in,
                              void* d_out, int out_size)
{
    const float4* hidden    = (const float4*)d_in[0];   // [B,S,H] f32
    const float4* w2v       = (const float4*)d_in[1];   // [VOCAB,WE] f32
    const int*    token_ids = (const int*)d_in[2];      // [B,S]
    const int*    word_ids  = (const int*)d_in[3];      // [B,W]
    float4*       out       = (float4*)d_out;           // [B,W,H+WE] f32

    seg_bounds_scatter<<<(B * S + 255) / 256, 256>>>(token_ids);   // 128 blocks
    embeddings_fused_kernel<<<B * WG, 256>>>(hidden, w2v, word_ids, out);
}

// round 8
// speedup vs baseline: 2.4766x; 1.0587x over previous
#include <cuda_runtime.h>

// Problem constants (B=64, S=512, H=768, W=MAX_WORD_LEN=256, VOCAB=50000, WE=300)
constexpr int B   = 64;
constexpr int S   = 512;
constexpr int H   = 768;
constexpr int W   = 256;
constexpr int WE  = 300;

constexpr int H4   = H  / 4;       // 192 float4 per transformer row
constexpr int WE4  = WE / 4;       // 75  float4 per w2v row
constexpr int OUT4 = H4 + WE4;     // 267 float4 per output row

constexpr int CH   = H4 / 32;      // 6 column chunks per lane (H part)
constexpr int CG   = (WE4 + 31) / 32;  // 3 gather chunks per lane

// Segment boundaries: g_start[b*(W+1) + w] = lower_bound(token_ids[b,:], w).
__device__ int g_start[B * (W + 1)];

// ---------------------------------------------------------------------------
// Kernel 1: scatter-based bounds. One thread per (b, s). For every word value
// w in (token[s-1], token[s]], lower_bound(w) == s. The last token thread
// also covers (token[S-1], W] -> S.
// ---------------------------------------------------------------------------
__global__ void __launch_bounds__(256)
seg_bounds_scatter(const int* __restrict__ token_ids)   // [B, S]
{
    const int idx = blockIdx.x * blockDim.x + threadIdx.x;
    if (idx >= B * S) return;
    const int b = idx >> 9;            // / S (S == 512)
    const int s = idx & (S - 1);

    const int cur  = token_ids[idx];
    const int prev = (s == 0) ? -1 : token_ids[idx - 1];

    int* __restrict__ srow = g_start + b * (W + 1);
    for (int w = prev + 1; w <= cur; ++w) srow[w] = s;
    if (s == S - 1) {
        for (int w = cur + 1; w <= W; ++w) srow[w] = S;
    }
}

// ---------------------------------------------------------------------------
// Kernel 2: ONE WARP per output row (b, w). Each lane owns 6 fixed float4
// column chunks of the H-part and 3 chunks of the w2v part. The gather loads
// are issued before the mean loop; the mean loop issues 6 independent
// coalesced loads per token. Per-lane MLP ~9-15 vs ~3 in the CTA-per-word
// layout — this is the latency-hiding fix the R7 profile asked for.
// ---------------------------------------------------------------------------
__global__ void __launch_bounds__(256)
embeddings_fused_kernel(const float4* __restrict__ hidden,     // [B, S, H4]
                        const float4* __restrict__ w2v,        // [VOCAB, WE4]
                        const int*    __restrict__ word_ids,   // [B, W]
                        float4*       __restrict__ out)        // [B, W, OUT4]
{
    const int warp = (blockIdx.x << 3) | (threadIdx.x >> 5);   // global warp id
    const int lane = threadIdx.x & 31;
    const int b    = warp >> 8;             // / W
    const int w    = warp & (W - 1);

    const int sidx  = b * (W + 1) + w;
    const int start = g_start[sidx];        // uniform across warp (broadcast)
    const int end   = g_start[sidx + 1];
    const int count = end - start;
    const float inv = (count > 0) ? (1.0f / (float)count) : 0.0f;
    const int wid   = word_ids[b * W + w];

    const float4* __restrict__ hbase = hidden + ((size_t)b * S + start) * H4 + lane;
    const float4* __restrict__ grow  = w2v + (size_t)wid * WE4;
    float4* __restrict__ orow        = out + (size_t)warp * OUT4;

    // --- issue the w2v gather loads first (independent, in flight during mean)
    float4 gv[CG];
    #pragma unroll
    for (int c = 0; c < CG; ++c) {
        const int j = lane + 32 * c;
        if (j < WE4) gv[c] = __ldg(grow + j);
    }

    // --- token-major segment mean: 6 independent coalesced loads per token
    float4 acc[CH];
    #pragma unroll
    for (int c = 0; c < CH; ++c) acc[c] = make_float4(0.f, 0.f, 0.f, 0.f);

    const float4* p = hbase;
    for (int t = 0; t < count; ++t, p += H4) {
        float4 v[CH];
        #pragma unroll
        for (int c = 0; c < CH; ++c) v[c] = __ldcs(p + 32 * c);
        #pragma unroll
        for (int c = 0; c < CH; ++c) {
            acc[c].x += v[c].x; acc[c].y += v[c].y;
            acc[c].z += v[c].z; acc[c].w += v[c].w;
        }
    }

    // --- write the mean part (coalesced 512B per chunk)
    #pragma unroll
    for (int c = 0; c < CH; ++c) {
        float4 r;
        r.x = acc[c].x * inv; r.y = acc[c].y * inv;
        r.z = acc[c].z * inv; r.w = acc[c].w * inv;
        __stcs(orow + lane + 32 * c, r);
    }

    // --- write the gather part
    #pragma unroll
    for (int c = 0; c < CG; ++c) {
        const int j = lane + 32 * c;
        if (j < WE4) __stcs(orow + H4 + j, gv[c]);
    }
}

extern "C" void kernel_launch(void* const* d_in, const int* in_sizes, int n_in,
                              void* d_out, int out_size)
{
    const float4* hidden    = (const float4*)d_in[0];   // [B,S,H] f32
    const float4* w2v       = (const float4*)d_in[1];   // [VOCAB,WE] f32
    const int*    token_ids = (const int*)d_in[2];      // [B,S]
    const int*    word_ids  = (const int*)d_in[3];      // [B,W]
    float4*       out       = (float4*)d_out;           // [B,W,H+WE] f32

    seg_bounds_scatter<<<(B * S + 255) / 256, 256>>>(token_ids);   // 128 blocks
    embeddings_fused_kernel<<<(B * W) / 8, 256>>>(hidden, w2v, word_ids, out);
}

// round 9
// speedup vs baseline: 2.7487x; 1.1099x over previous
#include <cuda_runtime.h>

// Problem constants (B=64, S=512, H=768, W=MAX_WORD_LEN=256, VOCAB=50000, WE=300)
constexpr int B   = 64;
constexpr int S   = 512;
constexpr int H   = 768;
constexpr int W   = 256;
constexpr int WE  = 300;

constexpr int H4   = H  / 4;       // 192 float4 per transformer row
constexpr int WE4  = WE / 4;       // 75  float4 per w2v row
constexpr int OUT4 = H4 + WE4;     // 267 float4 per output row

constexpr int CH   = 3;            // H-part chunks per half-warp-row (192/32/2)

// ---------------------------------------------------------------------------
// Warp-cooperative lower_bound over a sorted 512-int row.
// tv1 = trow[16*lane] must be preloaded (shared by multiple calls).
// Level 1: ballot localizes the answer to a 16-element window.
// Level 2: 16 lanes load the window; popc of the ballot finishes.
// ---------------------------------------------------------------------------
__device__ __forceinline__ int warp_lower_bound(const int* __restrict__ trow,
                                                int tv1, int target, int lane)
{
    const unsigned m1 = __ballot_sync(0xffffffffu, tv1 < target);
    const int nlt = __popc(m1);          // sampled points with value < target
    if (nlt == 0) return 0;              // trow[0] >= target
    const int base = 16 * (nlt - 1) + 1; // answer in [base, base+15] (or S)
    const int idx  = base + lane;
    const int v    = (lane < 16 && idx < S) ? trow[idx] : 0x7fffffff;
    const unsigned m2 = __ballot_sync(0xffffffffu, v < target);
    return base + __popc(m2);
}

// ---------------------------------------------------------------------------
// Single fused kernel. TWO warps per output row (b, w): half h in {0,1} owns
// H-chunks 3h..3h+2 and a slice of the w2v gather. Each warp computes its
// segment bounds with the warp-cooperative search (3 warp-wide loads, no
// per-thread binary search, no separate bounds kernel / launch gap).
// Ordering maximizes loads in flight: word_ids + w2v gather loads issue
// before the search; the mean loop issues 3 independent coalesced .cs loads
// per token. ~48 regs -> higher occupancy than the 64-reg R8 layout.
// ---------------------------------------------------------------------------
__global__ void __launch_bounds__(256)
embeddings_fused_kernel(const float4* __restrict__ hidden,     // [B, S, H4]
                        const float4* __restrict__ w2v,        // [VOCAB, WE4]
                        const int*    __restrict__ token_ids,  // [B, S]
                        const int*    __restrict__ word_ids,   // [B, W]
                        float4*       __restrict__ out)        // [B, W, OUT4]
{
    const int gwarp = (blockIdx.x << 3) | (threadIdx.x >> 5); // 0 .. 2*B*W-1
    const int lane  = threadIdx.x & 31;
    const int row   = gwarp >> 1;            // output row (b*W + w)
    const int h     = gwarp & 1;             // half: 0 or 1
    const int b     = row >> 8;              // / W
    const int w     = row & (W - 1);

    // --- issue gather loads first (independent of the segment search) ------
    const int wid = word_ids[row];           // uniform broadcast load
    const float4* __restrict__ grow = w2v + (size_t)wid * WE4;
    float4 gv0, gv1;
    int gj0, gj1;
    if (h == 0) { gj0 = lane;      gj1 = lane + 32; }   // chunks 0,1
    else        { gj0 = lane + 64; gj1 = WE4;       }   // chunk 2 (11 lanes)
    if (gj0 < WE4) gv0 = __ldg(grow + gj0);
    if (gj1 < WE4) gv1 = __ldg(grow + gj1);

    // --- warp-cooperative segment bounds ----------------------------------
    const int* __restrict__ trow = token_ids + b * S;
    const int tv1   = trow[lane << 4];       // sample trow[16*lane]
    const int start = warp_lower_bound(trow, tv1, w, lane);
    const int end   = warp_lower_bound(trow, tv1, w + 1, lane);
    const int count = end - start;
    const float inv = (count > 0) ? (1.0f / (float)count) : 0.0f;

    // --- token-major segment mean: 3 independent coalesced loads per token -
    const int col0 = lane + 32 * (3 * h);    // this warp's first column chunk
    const float4* p = hidden + ((size_t)b * S + start) * H4 + col0;

    float4 acc[CH];
    #pragma unroll
    for (int c = 0; c < CH; ++c) acc[c] = make_float4(0.f, 0.f, 0.f, 0.f);

    for (int t = 0; t < count; ++t, p += H4) {
        float4 v[CH];
        #pragma unroll
        for (int c = 0; c < CH; ++c) v[c] = __ldcs(p + 32 * c);
        #pragma unroll
        for (int c = 0; c < CH; ++c) {
            acc[c].x += v[c].x; acc[c].y += v[c].y;
            acc[c].z += v[c].z; acc[c].w += v[c].w;
        }
    }

    // --- write mean part (coalesced 512B per chunk) ------------------------
    float4* __restrict__ orow = out + (size_t)row * OUT4;
    #pragma unroll
    for (int c = 0; c < CH; ++c) {
        float4 r;
        r.x = acc[c].x * inv; r.y = acc[c].y * inv;
        r.z = acc[c].z * inv; r.w = acc[c].w * inv;
        __stcs(orow + col0 + 32 * c, r);
    }

    // --- write gather part -------------------------------------------------
    if (gj0 < WE4) __stcs(orow + H4 + gj0, gv0);
    if (gj1 < WE4) __stcs(orow + H4 + gj1, gv1);
}

extern "C" void kernel_launch(void* const* d_in, const int* in_sizes, int n_in,
                              void* d_out, int out_size)
{
    const float4* hidden    = (const float4*)d_in[0];   // [B,S,H] f32
    const float4* w2v       = (const float4*)d_in[1];   // [VOCAB,WE] f32
    const int*    token_ids = (const int*)d_in[2];      // [B,S]
    const int*    word_ids  = (const int*)d_in[3];      // [B,W]
    float4*       out       = (float4*)d_out;           // [B,W,H+WE] f32

    // 2 warps per row, 8 warps per CTA -> B*W/4 = 4096 CTAs
    embeddings_fused_kernel<<<(B * W * 2) / 8, 256>>>(hidden, w2v, token_ids,
                                                      word_ids, out);
}

// round 14
// speedup vs baseline: 2.9627x; 1.0779x over previous
#include <cuda_runtime.h>

// Problem constants (B=64, S=512, H=768, W=MAX_WORD_LEN=256, VOCAB=50000, WE=300)
constexpr int B   = 64;
constexpr int S   = 512;
constexpr int H   = 768;
constexpr int W   = 256;
constexpr int WE  = 300;

constexpr int H4   = H  / 4;       // 192 float4 per transformer row
constexpr int WE4  = WE / 4;       // 75  float4 per w2v row
constexpr int OUT4 = H4 + WE4;     // 267 float4 per output row

constexpr int CH   = 3;            // H-part chunks per half-row warp (192/32/2)

// ---------------------------------------------------------------------------
// Warp-cooperative lower_bound over a sorted 512-int row.
// tv1 = trow[16*lane] must be preloaded (shared by both calls).
// ---------------------------------------------------------------------------
__device__ __forceinline__ int warp_lower_bound(const int* __restrict__ trow,
                                                int tv1, int target, int lane)
{
    const unsigned m1 = __ballot_sync(0xffffffffu, tv1 < target);
    const int nlt = __popc(m1);          // sampled points with value < target
    if (nlt == 0) return 0;              // trow[0] >= target
    const int base = 16 * (nlt - 1) + 1; // answer in [base, base+15] (or S)
    const int idx  = base + lane;
    const int v    = (lane < 16 && idx < S) ? trow[idx] : 0x7fffffff;
    const unsigned m2 = __ballot_sync(0xffffffffu, v < target);
    return base + __popc(m2);
}

// ---------------------------------------------------------------------------
// Single fused kernel, TWO warps per output row (b, w); half h owns H-chunks
// 3h..3h+2 plus a slice of the w2v gather.
//
// R10 changes vs R9:
//  * w2v gather is load->store IMMEDIATELY at the top (transient registers,
//    not held live across the mean loop) — frees 8 regs of loop-live state.
//  * __launch_bounds__(256, 6) caps regs at 42 -> 6 CTAs/SM (75% theor. occ).
//    Latency hiding now comes from warp count instead of per-thread MLP.
// ---------------------------------------------------------------------------
__global__ void __launch_bounds__(256, 6)
embeddings_fused_kernel(const float4* __restrict__ hidden,     // [B, S, H4]
                        const float4* __restrict__ w2v,        // [VOCAB, WE4]
                        const int*    __restrict__ token_ids,  // [B, S]
                        const int*    __restrict__ word_ids,   // [B, W]
                        float4*       __restrict__ out)        // [B, W, OUT4]
{
    const int gwarp = (blockIdx.x << 3) | (threadIdx.x >> 5); // 0 .. 2*B*W-1
    const int lane  = threadIdx.x & 31;
    const int row   = gwarp >> 1;            // output row (b*W + w)
    const int h     = gwarp & 1;             // half: 0 or 1
    const int b     = row >> 8;              // / W
    const int w     = row & (W - 1);

    float4* __restrict__ orow = out + (size_t)row * OUT4;

    // --- w2v gather: load -> store immediately (registers stay transient) --
    {
        const int wid = word_ids[row];       // uniform broadcast load
        const float4* __restrict__ grow = w2v + (size_t)wid * WE4;
        int gj0, gj1;
        if (h == 0) { gj0 = lane;      gj1 = lane + 32; }   // chunks 0,1
        else        { gj0 = lane + 64; gj1 = WE4;       }   // chunk 2 (11 lanes)
        if (gj0 < WE4) __stcs(orow + H4 + gj0, __ldg(grow + gj0));
        if (gj1 < WE4) __stcs(orow + H4 + gj1, __ldg(grow + gj1));
    }

    // --- warp-cooperative segment bounds -----------------------------------
    const int* __restrict__ trow = token_ids + b * S;
    const int tv1   = trow[lane << 4];       // sample trow[16*lane]
    const int start = warp_lower_bound(trow, tv1, w, lane);
    const int end   = warp_lower_bound(trow, tv1, w + 1, lane);
    const int count = end - start;
    const float inv = (count > 0) ? (1.0f / (float)count) : 0.0f;

    // --- token-major segment mean: 3 independent coalesced loads per token -
    const int col0 = lane + 32 * (3 * h);    // this warp's first column chunk
    const float4* p = hidden + ((size_t)b * S + start) * H4 + col0;

    float4 acc[CH];
    #pragma unroll
    for (int c = 0; c < CH; ++c) acc[c] = make_float4(0.f, 0.f, 0.f, 0.f);

    for (int t = 0; t < count; ++t, p += H4) {
        float4 v[CH];
        #pragma unroll
        for (int c = 0; c < CH; ++c) v[c] = __ldcs(p + 32 * c);
        #pragma unroll
        for (int c = 0; c < CH; ++c) {
            acc[c].x += v[c].x; acc[c].y += v[c].y;
            acc[c].z += v[c].z; acc[c].w += v[c].w;
        }
    }

    // --- write mean part (coalesced 512B per chunk) ------------------------
    #pragma unroll
    for (int c = 0; c < CH; ++c) {
        float4 r;
        r.x = acc[c].x * inv; r.y = acc[c].y * inv;
        r.z = acc[c].z * inv; r.w = acc[c].w * inv;
        __stcs(orow + col0 + 32 * c, r);
    }
}

extern "C" void kernel_launch(void* const* d_in, const int* in_sizes, int n_in,
                              void* d_out, int out_size)
{
    const float4* hidden    = (const float4*)d_in[0];   // [B,S,H] f32
    const float4* w2v       = (const float4*)d_in[1];   // [VOCAB,WE] f32
    const int*    token_ids = (const int*)d_in[2];      // [B,S]
    const int*    word_ids  = (const int*)d_in[3];      // [B,W]
    float4*       out       = (float4*)d_out;           // [B,W,H+WE] f32

    // 2 warps per row, 8 warps per CTA -> 4096 CTAs
    embeddings_fused_kernel<<<(B * W * 2) / 8, 256>>>(hidden, w2v, token_ids,
                                                      word_ids, out);
}